// round 14
// baseline (speedup 1.0000x reference)
#include <cuda_runtime.h>
#include <cuda_fp16.h>
#include <math.h>

#define S_LEN 2048
#define HID   2048
#define NH    32
#define NKV   8
#define HD    64

// ---------------- static scratch ----------------
static __device__ float  g_scale[4];
static __device__ float  g_part[4 * 256];
static __device__ __half g_xh[S_LEN * HID];            // fp16 activations
static __device__ __half g_wqkv[3072 * HID];           // concat ternary: Q[0:2048) K[2048:2560) V[2560:3072)
static __device__ __half g_wo[HID * HID];
static __device__ __half g_qh[S_LEN * HID];            // Q (rope'd, pre-scaled 1/8)
static __device__ __half g_kh[S_LEN * NKV * HD];       // K (rope'd)
static __device__ __half g_vth[NKV * HD * S_LEN];      // V TRANSPOSED [d][seq]
static __device__ __half g_atth[S_LEN * HID];          // attention out

// ---------------- helpers ----------------
__device__ __forceinline__ unsigned pack_half2(float lo, float hi) {
    __half2 h = __floats2half2_rn(lo, hi);
    return *(unsigned*)&h;
}

__device__ __forceinline__ void mma_f16(float c[4], const unsigned a[4], const unsigned b[2]) {
    asm volatile(
        "mma.sync.aligned.m16n8k16.row.col.f32.f16.f16.f32 "
        "{%0,%1,%2,%3}, {%4,%5,%6,%7}, {%8,%9}, {%0,%1,%2,%3};"
        : "+f"(c[0]), "+f"(c[1]), "+f"(c[2]), "+f"(c[3])
        : "r"(a[0]), "r"(a[1]), "r"(a[2]), "r"(a[3]), "r"(b[0]), "r"(b[1]));
}

__device__ __forceinline__ void ldsm4(unsigned r[4], const __half* p) {
    unsigned addr = (unsigned)__cvta_generic_to_shared(p);
    asm volatile("ldmatrix.sync.aligned.m8n8.x4.shared.b16 {%0,%1,%2,%3}, [%4];"
                 : "=r"(r[0]), "=r"(r[1]), "=r"(r[2]), "=r"(r[3]) : "r"(addr));
}

__device__ __forceinline__ void cp_async16(void* smem_dst, const void* gptr) {
    unsigned s = (unsigned)__cvta_generic_to_shared(smem_dst);
    asm volatile("cp.async.cg.shared.global [%0], [%1], 16;" :: "r"(s), "l"(gptr));
}
__device__ __forceinline__ void cp_commit() { asm volatile("cp.async.commit_group;"); }
template <int N>
__device__ __forceinline__ void cp_wait() { asm volatile("cp.async.wait_group %0;" :: "n"(N)); }

// ---------------- fused absmean (deterministic two-stage) ----------------
__global__ void absmean_all_partial(const float* __restrict__ wq, const float* __restrict__ wk,
                                    const float* __restrict__ wv, const float* __restrict__ wo,
                                    float* __restrict__ part) {
    __shared__ float red[256];
    int t = blockIdx.y;
    const float* w = t == 0 ? wq : t == 1 ? wk : t == 2 ? wv : wo;
    int n = (t == 0 || t == 3) ? HID * HID : NKV * HD * HID;
    float s0 = 0.f, s1 = 0.f, s2 = 0.f, s3 = 0.f;
    int stride = gridDim.x * blockDim.x;
    for (int i = blockIdx.x * blockDim.x + threadIdx.x; i < n; i += 4 * stride) {
        s0 += fabsf(w[i]);
        if (i + stride < n)     s1 += fabsf(w[i + stride]);
        if (i + 2 * stride < n) s2 += fabsf(w[i + 2 * stride]);
        if (i + 3 * stride < n) s3 += fabsf(w[i + 3 * stride]);
    }
    red[threadIdx.x] = (s0 + s1) + (s2 + s3);
    __syncthreads();
    for (int o = 128; o > 0; o >>= 1) {
        if (threadIdx.x < o) red[threadIdx.x] += red[threadIdx.x + o];
        __syncthreads();
    }
    if (threadIdx.x == 0) part[t * 256 + blockIdx.x] = red[0];
}

__global__ void absmean_all_final(const float* __restrict__ part, float* __restrict__ scale) {
    __shared__ float red[256];
    int t = blockIdx.x;
    int n = (t == 0 || t == 3) ? HID * HID : NKV * HD * HID;
    red[threadIdx.x] = part[t * 256 + threadIdx.x];
    __syncthreads();
    for (int o = 128; o > 0; o >>= 1) {
        if (threadIdx.x < o) red[threadIdx.x] += red[threadIdx.x + o];
        __syncthreads();
    }
    if (threadIdx.x == 0) scale[t] = red[0] / (float)n + 1e-6f;
}

// ---------------- fused quantize (w->ternary fp16) + x->fp16 convert ----------------
__global__ void prep_all_h(const float* __restrict__ wq, const float* __restrict__ wk,
                           const float* __restrict__ wv, const float* __restrict__ wo,
                           const float* __restrict__ x,
                           __half* __restrict__ oqkv, __half* __restrict__ oo,
                           __half* __restrict__ ox,
                           const float* __restrict__ scales) {
    int t = blockIdx.y;
    const float4* w;
    __half* o;
    int n4;
    bool quant = t < 4;
    if (t == 0)      { w = (const float4*)wq; o = oqkv;               n4 = (HID * HID) >> 2; }
    else if (t == 1) { w = (const float4*)wk; o = oqkv + 2048 * HID;  n4 = (NKV * HD * HID) >> 2; }
    else if (t == 2) { w = (const float4*)wv; o = oqkv + 2560 * HID;  n4 = (NKV * HD * HID) >> 2; }
    else if (t == 3) { w = (const float4*)wo; o = oo;                 n4 = (HID * HID) >> 2; }
    else             { w = (const float4*)x;  o = ox;                 n4 = (S_LEN * HID) >> 2; }
    float inv = quant ? 1.f / scales[t] : 1.f;
    int stride = gridDim.x * blockDim.x;
    for (int i0 = blockIdx.x * blockDim.x + threadIdx.x; i0 < n4; i0 += 4 * stride) {
        float4 v[4];
        int cnt = 0;
#pragma unroll
        for (int j = 0; j < 4; j++) {
            int idx = i0 + j * stride;
            if (idx < n4) { v[j] = w[idx]; cnt = j + 1; }
        }
#pragma unroll
        for (int j = 0; j < 4; j++) {
            int idx = i0 + j * stride;
            if (j < cnt && idx < n4) {
                unsigned u0, u1;
                if (quant) {
                    u0 = pack_half2(rintf(fminf(fmaxf(v[j].x * inv, -1.f), 1.f)),
                                    rintf(fminf(fmaxf(v[j].y * inv, -1.f), 1.f)));
                    u1 = pack_half2(rintf(fminf(fmaxf(v[j].z * inv, -1.f), 1.f)),
                                    rintf(fminf(fmaxf(v[j].w * inv, -1.f), 1.f)));
                } else {
                    u0 = pack_half2(v[j].x, v[j].y);
                    u1 = pack_half2(v[j].z, v[j].w);
                }
                ((uint2*)o)[idx] = make_uint2(u0, u1);
            }
        }
    }
}

// ---------------- GEMM common: 128x128 block, 64x32 warp tile, 3 stages, 3 CTAs/SM ----------------
#define GBM 128
#define GBN 128
#define GBKH 32
#define PADH 40
#define STAGES 3
#define HGEMM_SMEM (STAGES * 2 * GBM * PADH * 2)

struct Frag { float c[4][4][4]; };

__device__ __forceinline__ void hgemm_mainloop(const __half* __restrict__ Ap,
                                               const __half* __restrict__ Wp,
                                               __half* Ah, __half* Bh,
                                               int K, int tid, int wm, int wn,
                                               int lane, Frag& F) {
    const int a_row = lane & 15;
    const int a_col = (lane >> 4) * 8;
    const int b_sel = lane >> 4;
    const int b_row = lane & 7;
    const int b_col = ((lane >> 3) & 1) * 8;

    const int ntiles = K / GBKH;

    auto load_tile = [&](int stage, int k0) {
#pragma unroll
        for (int i = 0; i < 2; i++) {
            int ch = tid + i * 256;
            int r = ch >> 2, c8 = (ch & 3) * 8;
            cp_async16(Ah + stage * GBM * PADH + r * PADH + c8, Ap + (size_t)r * K + k0 + c8);
            cp_async16(Bh + stage * GBM * PADH + r * PADH + c8, Wp + (size_t)r * K + k0 + c8);
        }
    };

#pragma unroll
    for (int s = 0; s < STAGES - 1; s++) {
        load_tile(s, s * GBKH);
        cp_commit();
    }

    for (int kt = 0; kt < ntiles; kt++) {
        cp_wait<STAGES - 2>();
        __syncthreads();

        int kn = kt + STAGES - 1;
        if (kn < ntiles) load_tile(kn % STAGES, kn * GBKH);
        cp_commit();

        const __half* As = Ah + (kt % STAGES) * GBM * PADH;
        const __half* Bs = Bh + (kt % STAGES) * GBM * PADH;

#pragma unroll
        for (int ks = 0; ks < GBKH; ks += 16) {
            unsigned a[4][4], b[4][2];
#pragma unroll
            for (int mt = 0; mt < 4; mt++)
                ldsm4(a[mt], As + (wm + mt * 16 + a_row) * PADH + ks + a_col);
#pragma unroll
            for (int j = 0; j < 2; j++) {
                unsigned bb[4];
                ldsm4(bb, Bs + (wn + (2 * j + b_sel) * 8 + b_row) * PADH + ks + b_col);
                b[2 * j][0] = bb[0]; b[2 * j][1] = bb[1];
                b[2 * j + 1][0] = bb[2]; b[2 * j + 1][1] = bb[3];
            }
#pragma unroll
            for (int mt = 0; mt < 4; mt++)
#pragma unroll
                for (int nt = 0; nt < 4; nt++)
                    mma_f16(F.c[mt][nt], a[mt], b[nt]);
        }
        // no trailing __syncthreads: buffer kt%STAGES is next written at
        // iteration kt+1, after that iteration's top __syncthreads.
    }
}

// ---------------- fused QKV GEMM (3 CTAs/SM -> 384 blocks = one wave) ----------------
__global__ __launch_bounds__(256, 3) void hgemm_qkv(const __half* __restrict__ A,
                                                    const __half* __restrict__ Wqkv,
                                                    __half* __restrict__ Qout,
                                                    __half* __restrict__ Kout,
                                                    __half* __restrict__ Vtout,
                                                    const float* __restrict__ scales) {
    extern __shared__ __half hsm[];
    __half* Ah = hsm;
    __half* Bh = hsm + STAGES * GBM * PADH;

    const int tid = threadIdx.x;
    const int bx = blockIdx.x;
    const int bm = blockIdx.y * GBM;
    const int bn = bx * GBN;
    const int warp = tid >> 5, lane = tid & 31;
    const int wm = (warp & 1) * 64;
    const int wn = (warp >> 1) * 32;
    const int g = lane >> 2, tg = lane & 3;

    Frag F = {};
    hgemm_mainloop(A + (size_t)bm * HID, Wqkv + (size_t)bn * HID, Ah, Bh,
                   HID, tid, wm, wn, lane, F);

    const int region = bx < 16 ? 0 : (bx < 20 ? 1 : 2);
    const float scale = scales[region];

#pragma unroll
    for (int mt = 0; mt < 4; mt++) {
#pragma unroll
        for (int nt = 0; nt < 4; nt++) {
            int row = bm + wm + mt * 16 + g;
            int cb = wn + nt * 8 + 2 * tg;
            float v0 = F.c[mt][nt][0] * scale, v1 = F.c[mt][nt][1] * scale;
            float v2 = F.c[mt][nt][2] * scale, v3 = F.c[mt][nt][3] * scale;
            if (region == 0) {
                int col = bn + cb;
                *(unsigned*)(Qout + (size_t)row * HID + col) = pack_half2(v0, v1);
                *(unsigned*)(Qout + (size_t)(row + 8) * HID + col) = pack_half2(v2, v3);
            } else if (region == 1) {
                int col = bn - 2048 + cb;
                *(unsigned*)(Kout + (size_t)row * (NKV * HD) + col) = pack_half2(v0, v1);
                *(unsigned*)(Kout + (size_t)(row + 8) * (NKV * HD) + col) = pack_half2(v2, v3);
            } else {
                int col = bn - 2560 + cb;
                Vtout[(size_t)col * S_LEN + row]           = __float2half_rn(v0);
                Vtout[(size_t)(col + 1) * S_LEN + row]     = __float2half_rn(v1);
                Vtout[(size_t)col * S_LEN + row + 8]       = __float2half_rn(v2);
                Vtout[(size_t)(col + 1) * S_LEN + row + 8] = __float2half_rn(v3);
            }
        }
    }
}

// ---------------- output GEMM (fp32 out) ----------------
__global__ __launch_bounds__(256, 3) void hgemm_out(const __half* __restrict__ A,
                                                    const __half* __restrict__ W,
                                                    float* __restrict__ C,
                                                    const float* __restrict__ scale_p) {
    extern __shared__ __half hsm[];
    __half* Ah = hsm;
    __half* Bh = hsm + STAGES * GBM * PADH;

    const int tid = threadIdx.x;
    const float scale = *scale_p;
    const int bm = blockIdx.y * GBM;
    const int bn = blockIdx.x * GBN;
    const int warp = tid >> 5, lane = tid & 31;
    const int wm = (warp & 1) * 64;
    const int wn = (warp >> 1) * 32;
    const int g = lane >> 2, tg = lane & 3;

    Frag F = {};
    hgemm_mainloop(A + (size_t)bm * HID, W + (size_t)bn * HID, Ah, Bh,
                   HID, tid, wm, wn, lane, F);

#pragma unroll
    for (int mt = 0; mt < 4; mt++) {
#pragma unroll
        for (int nt = 0; nt < 4; nt++) {
            int row = bm + wm + mt * 16 + g;
            int col = bn + wn + nt * 8 + 2 * tg;
            *(float2*)(C + (size_t)row * HID + col) =
                make_float2(F.c[mt][nt][0] * scale, F.c[mt][nt][1] * scale);
            *(float2*)(C + (size_t)(row + 8) * HID + col) =
                make_float2(F.c[mt][nt][2] * scale, F.c[mt][nt][3] * scale);
        }
    }
}

// ---------------- fused RoPE over Q and K (one launch) ----------------
__global__ void rope_qk(__half* __restrict__ q, __half* __restrict__ k,
                        const int* __restrict__ pos_ids) {
    int idx = blockIdx.x * blockDim.x + threadIdx.x;
    const int qtotal = S_LEN * NH * 32;
    const int total = qtotal + S_LEN * NKV * 32;
    if (idx >= total) return;
    __half* x;
    int nheads;
    float s_mul;
    int li;
    if (idx < qtotal) { x = q; nheads = NH; s_mul = 0.125f; li = idx; }
    else { x = k; nheads = NKV; s_mul = 1.0f; li = idx - qtotal; }
    int i = li & 31;
    int h = (li >> 5) % nheads;
    int s = li / (32 * nheads);
    float pos = (float)pos_ids[s];
    float inv_freq = powf(10000.f, -(float)(2 * i) / 64.f);
    float ang = pos * inv_freq;
    float c = cosf(ang), sn = sinf(ang);
    __half* base = x + ((size_t)s * nheads + h) * HD;
    float x1 = __half2float(base[i]), x2 = __half2float(base[i + 32]);
    base[i]      = __float2half_rn(s_mul * (x1 * c - x2 * sn));
    base[i + 32] = __float2half_rn(s_mul * (x2 * c + x1 * sn));
}

// ---------------- fp16 flash attention: 128 q-rows/block, 8 warps, KV tile 128 ----------------
#define KPADH 72
#define VPADT 136
#define FAH_SMEM ((2 * 128 * KPADH + 2 * 64 * VPADT) * 2)

__global__ __launch_bounds__(256) void flash_h(const __half* __restrict__ Qh,
                                               const __half* __restrict__ Kg,
                                               const __half* __restrict__ Vtg,
                                               const float* __restrict__ mask,
                                               __half* __restrict__ O) {
    extern __shared__ __half hs[];
    __half (*Ks)[128][KPADH] = (__half(*)[128][KPADH])hs;
    __half (*Vs)[64][VPADT] = (__half(*)[64][VPADT])(hs + 2 * 128 * KPADH);

    const int tid = threadIdx.x;
    const int warp = tid >> 5, lane = tid & 31;
    const int g = lane >> 2, tg = lane & 3;
    const int wm = warp * 16;          // 8 warps -> 128 q rows

    const int h = blockIdx.y;
    const int kvh = h >> 2;
    const int qbase = blockIdx.x * 128;

    auto load_tiles = [&](int buf, int t) {
#pragma unroll
        for (int u = 0; u < 4; u++) {
            int slot = tid + u * 256;
            int kr = slot >> 3, kc = (slot & 7) * 8;
            cp_async16(&Ks[buf][kr][kc], Kg + (size_t)(t + kr) * (NKV * HD) + kvh * HD + kc);
            int vr = slot >> 4, vc = (slot & 15) * 8;
            cp_async16(&Vs[buf][vr][vc], Vtg + (size_t)(kvh * HD + vr) * S_LEN + t + vc);
        }
    };

    unsigned qa[4][4];
    {
        const __half* Qp = Qh + (size_t)qbase * HID + h * HD;
        const int r0 = wm + g, r1 = wm + g + 8;
#pragma unroll
        for (int ks = 0; ks < 4; ks++) {
            qa[ks][0] = *(const unsigned*)(Qp + (size_t)r0 * HID + ks * 16 + 2 * tg);
            qa[ks][1] = *(const unsigned*)(Qp + (size_t)r1 * HID + ks * 16 + 2 * tg);
            qa[ks][2] = *(const unsigned*)(Qp + (size_t)r0 * HID + ks * 16 + 2 * tg + 8);
            qa[ks][3] = *(const unsigned*)(Qp + (size_t)r1 * HID + ks * 16 + 2 * tg + 8);
        }
    }

    float co[8][4] = {};
    float m_g = -1e30f, m_g8 = -1e30f, l_g = 0.f, l_g8 = 0.f;

    load_tiles(0, 0);
    cp_commit();

    for (int ti = 0; ti < S_LEN / 128; ti++) {
        const int t = ti * 128;
        if (ti + 1 < S_LEN / 128) load_tiles((ti + 1) & 1, t + 128);
        cp_commit();
        cp_wait<1>();
        __syncthreads();

        const int buf = ti & 1;

        float cs[16][4] = {};
#pragma unroll
        for (int ks = 0; ks < 4; ks++) {
#pragma unroll
            for (int nt = 0; nt < 16; nt++) {
                unsigned b[2];
                b[0] = *(const unsigned*)&Ks[buf][nt * 8 + g][ks * 16 + 2 * tg];
                b[1] = *(const unsigned*)&Ks[buf][nt * 8 + g][ks * 16 + 2 * tg + 8];
                mma_f16(cs[nt], qa[ks], b);
            }
        }

        float mloc_g = -1e30f, mloc_g8 = -1e30f;
#pragma unroll
        for (int nt = 0; nt < 16; nt++) {
            float mk0 = __ldg(mask + t + nt * 8 + 2 * tg);
            float mk1 = __ldg(mask + t + nt * 8 + 2 * tg + 1);
            cs[nt][0] += mk0; cs[nt][1] += mk1;
            cs[nt][2] += mk0; cs[nt][3] += mk1;
            mloc_g  = fmaxf(mloc_g,  fmaxf(cs[nt][0], cs[nt][1]));
            mloc_g8 = fmaxf(mloc_g8, fmaxf(cs[nt][2], cs[nt][3]));
        }
        mloc_g  = fmaxf(mloc_g,  __shfl_xor_sync(0xffffffff, mloc_g, 1));
        mloc_g  = fmaxf(mloc_g,  __shfl_xor_sync(0xffffffff, mloc_g, 2));
        mloc_g8 = fmaxf(mloc_g8, __shfl_xor_sync(0xffffffff, mloc_g8, 1));
        mloc_g8 = fmaxf(mloc_g8, __shfl_xor_sync(0xffffffff, mloc_g8, 2));

        float mn_g  = fmaxf(m_g,  mloc_g);
        float mn_g8 = fmaxf(m_g8, mloc_g8);
        float corr_g  = __expf(m_g - mn_g);
        float corr_g8 = __expf(m_g8 - mn_g8);

        float sum_g = 0.f, sum_g8 = 0.f;
#pragma unroll
        for (int nt = 0; nt < 16; nt++) {
            cs[nt][0] = __expf(cs[nt][0] - mn_g);
            cs[nt][1] = __expf(cs[nt][1] - mn_g);
            cs[nt][2] = __expf(cs[nt][2] - mn_g8);
            cs[nt][3] = __expf(cs[nt][3] - mn_g8);
            sum_g  += cs[nt][0] + cs[nt][1];
            sum_g8 += cs[nt][2] + cs[nt][3];
        }
#pragma unroll
        for (int nt = 0; nt < 8; nt++) {
            co[nt][0] *= corr_g;  co[nt][1] *= corr_g;
            co[nt][2] *= corr_g8; co[nt][3] *= corr_g8;
        }
        sum_g  += __shfl_xor_sync(0xffffffff, sum_g, 1);
        sum_g  += __shfl_xor_sync(0xffffffff, sum_g, 2);
        sum_g8 += __shfl_xor_sync(0xffffffff, sum_g8, 1);
        sum_g8 += __shfl_xor_sync(0xffffffff, sum_g8, 2);
        l_g  = l_g * corr_g + sum_g;
        l_g8 = l_g8 * corr_g8 + sum_g8;
        m_g = mn_g; m_g8 = mn_g8;

#pragma unroll
        for (int kk = 0; kk < 8; kk++) {
            unsigned a[4];
            a[0] = pack_half2(cs[2 * kk][0],     cs[2 * kk][1]);
            a[1] = pack_half2(cs[2 * kk][2],     cs[2 * kk][3]);
            a[2] = pack_half2(cs[2 * kk + 1][0], cs[2 * kk + 1][1]);
            a[3] = pack_half2(cs[2 * kk + 1][2], cs[2 * kk + 1][3]);
#pragma unroll
            for (int nt = 0; nt < 8; nt++) {
                unsigned b[2];
                b[0] = *(const unsigned*)&Vs[buf][nt * 8 + g][kk * 16 + 2 * tg];
                b[1] = *(const unsigned*)&Vs[buf][nt * 8 + g][kk * 16 + 2 * tg + 8];
                mma_f16(co[nt], a, b);
            }
        }
        __syncthreads();   // required: next iteration's cp.async into buf^1 is
                           // issued before the top sync of that iteration.
    }

    const float inv_g  = 1.f / l_g;
    const float inv_g8 = 1.f / l_g8;
    const int row0 = qbase + wm + g;
#pragma unroll
    for (int nt = 0; nt < 8; nt++) {
        int col = h * HD + nt * 8 + 2 * tg;
        *(unsigned*)(O + (size_t)row0 * HID + col) =
            pack_half2(co[nt][0] * inv_g, co[nt][1] * inv_g);
        *(unsigned*)(O + (size_t)(row0 + 8) * HID + col) =
            pack_half2(co[nt][2] * inv_g8, co[nt][3] * inv_g8);
    }
}

// ---------------- host launcher ----------------
extern "C" void kernel_launch(void* const* d_in, const int* in_sizes, int n_in,
                              void* d_out, int out_size) {
    const float* x    = (const float*)d_in[0];
    const float* mask = (const float*)d_in[1];
    const int*   pos  = (const int*)d_in[2];
    const float* wq   = (const float*)d_in[3];
    const float* wk   = (const float*)d_in[4];
    const float* wv   = (const float*)d_in[5];
    const float* wo   = (const float*)d_in[6];
    float* out = (float*)d_out;

    float *pscale, *ppart;
    __half *pxh, *pwqkv, *pwo, *pqh, *pkh, *pvth, *patth;
    cudaGetSymbolAddress((void**)&pscale, g_scale);
    cudaGetSymbolAddress((void**)&ppart,  g_part);
    cudaGetSymbolAddress((void**)&pxh,    g_xh);
    cudaGetSymbolAddress((void**)&pwqkv,  g_wqkv);
    cudaGetSymbolAddress((void**)&pwo,    g_wo);
    cudaGetSymbolAddress((void**)&pqh,    g_qh);
    cudaGetSymbolAddress((void**)&pkh,    g_kh);
    cudaGetSymbolAddress((void**)&pvth,   g_vth);
    cudaGetSymbolAddress((void**)&patth,  g_atth);

    cudaFuncSetAttribute(hgemm_qkv, cudaFuncAttributeMaxDynamicSharedMemorySize, HGEMM_SMEM);
    cudaFuncSetAttribute(hgemm_out, cudaFuncAttributeMaxDynamicSharedMemorySize, HGEMM_SMEM);
    cudaFuncSetAttribute(flash_h, cudaFuncAttributeMaxDynamicSharedMemorySize, FAH_SMEM);

    // scales
    absmean_all_partial<<<dim3(256, 4), 256>>>(wq, wk, wv, wo, ppart);
    absmean_all_final<<<4, 256>>>(ppart, pscale);

    // fused pre-pass: weight quantize + x convert in one launch
    prep_all_h<<<dim3(256, 5), 256>>>(wq, wk, wv, wo, x, pwqkv, pwo, pxh, pscale);

    // fused QKV projection (128x128 tiles, 3 CTAs/SM, 384 blocks = one wave)
    hgemm_qkv<<<dim3(24, 16), 256, HGEMM_SMEM>>>(pxh, pwqkv, pqh, pkh, pvth, pscale);

    // RoPE (Q pre-scaled by 1/sqrt(64)), single launch
    rope_qk<<<(S_LEN * (NH + NKV) * 32 + 255) / 256, 256>>>(pqh, pkh, pos);

    // flash attention (128 q-rows x 128 kv tile, 8 warps)
    flash_h<<<dim3(S_LEN / 128, NH), 256, FAH_SMEM>>>(pqh, pkh, pvth, mask, patth);

    // output projection
    hgemm_out<<<dim3(16, 16), 256, HGEMM_SMEM>>>(patth, pwo, out, pscale + 3);
}

// round 16
// speedup vs baseline: 1.1751x; 1.1751x over previous
#include <cuda_runtime.h>
#include <cuda_fp16.h>
#include <math.h>

#define S_LEN 2048
#define HID   2048
#define NH    32
#define NKV   8
#define HD    64

// ---------------- static scratch ----------------
static __device__ float  g_scale[4];
static __device__ float  g_part[4 * 256];
static __device__ __half g_xh[S_LEN * HID];            // fp16 activations
static __device__ __half g_wqkv[3072 * HID];           // concat ternary: Q[0:2048) K[2048:2560) V[2560:3072)
static __device__ __half g_wo[HID * HID];
static __device__ __half g_qh[S_LEN * HID];            // Q (rope'd, pre-scaled 1/8)
static __device__ __half g_kh[S_LEN * NKV * HD];       // K (rope'd)
static __device__ __half g_vth[NKV * HD * S_LEN];      // V TRANSPOSED [d][seq]
static __device__ __half g_atth[S_LEN * HID];          // attention out

// ---------------- helpers ----------------
__device__ __forceinline__ unsigned pack_half2(float lo, float hi) {
    __half2 h = __floats2half2_rn(lo, hi);
    return *(unsigned*)&h;
}

__device__ __forceinline__ void mma_f16(float c[4], const unsigned a[4], const unsigned b[2]) {
    asm volatile(
        "mma.sync.aligned.m16n8k16.row.col.f32.f16.f16.f32 "
        "{%0,%1,%2,%3}, {%4,%5,%6,%7}, {%8,%9}, {%0,%1,%2,%3};"
        : "+f"(c[0]), "+f"(c[1]), "+f"(c[2]), "+f"(c[3])
        : "r"(a[0]), "r"(a[1]), "r"(a[2]), "r"(a[3]), "r"(b[0]), "r"(b[1]));
}

__device__ __forceinline__ void ldsm4(unsigned r[4], const __half* p) {
    unsigned addr = (unsigned)__cvta_generic_to_shared(p);
    asm volatile("ldmatrix.sync.aligned.m8n8.x4.shared.b16 {%0,%1,%2,%3}, [%4];"
                 : "=r"(r[0]), "=r"(r[1]), "=r"(r[2]), "=r"(r[3]) : "r"(addr));
}

__device__ __forceinline__ void cp_async16(void* smem_dst, const void* gptr) {
    unsigned s = (unsigned)__cvta_generic_to_shared(smem_dst);
    asm volatile("cp.async.cg.shared.global [%0], [%1], 16;" :: "r"(s), "l"(gptr));
}
__device__ __forceinline__ void cp_commit() { asm volatile("cp.async.commit_group;"); }
template <int N>
__device__ __forceinline__ void cp_wait() { asm volatile("cp.async.wait_group %0;" :: "n"(N)); }

// ---------------- fused absmean (deterministic two-stage) ----------------
__global__ void absmean_all_partial(const float* __restrict__ wq, const float* __restrict__ wk,
                                    const float* __restrict__ wv, const float* __restrict__ wo,
                                    float* __restrict__ part) {
    __shared__ float red[256];
    int t = blockIdx.y;
    const float* w = t == 0 ? wq : t == 1 ? wk : t == 2 ? wv : wo;
    int n = (t == 0 || t == 3) ? HID * HID : NKV * HD * HID;
    float s0 = 0.f, s1 = 0.f, s2 = 0.f, s3 = 0.f;
    int stride = gridDim.x * blockDim.x;
    for (int i = blockIdx.x * blockDim.x + threadIdx.x; i < n; i += 4 * stride) {
        s0 += fabsf(w[i]);
        if (i + stride < n)     s1 += fabsf(w[i + stride]);
        if (i + 2 * stride < n) s2 += fabsf(w[i + 2 * stride]);
        if (i + 3 * stride < n) s3 += fabsf(w[i + 3 * stride]);
    }
    red[threadIdx.x] = (s0 + s1) + (s2 + s3);
    __syncthreads();
    for (int o = 128; o > 0; o >>= 1) {
        if (threadIdx.x < o) red[threadIdx.x] += red[threadIdx.x + o];
        __syncthreads();
    }
    if (threadIdx.x == 0) part[t * 256 + blockIdx.x] = red[0];
}

__global__ void absmean_all_final(const float* __restrict__ part, float* __restrict__ scale) {
    __shared__ float red[256];
    int t = blockIdx.x;
    int n = (t == 0 || t == 3) ? HID * HID : NKV * HD * HID;
    red[threadIdx.x] = part[t * 256 + threadIdx.x];
    __syncthreads();
    for (int o = 128; o > 0; o >>= 1) {
        if (threadIdx.x < o) red[threadIdx.x] += red[threadIdx.x + o];
        __syncthreads();
    }
    if (threadIdx.x == 0) scale[t] = red[0] / (float)n + 1e-6f;
}

// ---------------- fused quantize (w->ternary fp16) + x->fp16 convert ----------------
__global__ void prep_all_h(const float* __restrict__ wq, const float* __restrict__ wk,
                           const float* __restrict__ wv, const float* __restrict__ wo,
                           const float* __restrict__ x,
                           __half* __restrict__ oqkv, __half* __restrict__ oo,
                           __half* __restrict__ ox,
                           const float* __restrict__ scales) {
    int t = blockIdx.y;
    const float4* w;
    __half* o;
    int n4;
    bool quant = t < 4;
    if (t == 0)      { w = (const float4*)wq; o = oqkv;               n4 = (HID * HID) >> 2; }
    else if (t == 1) { w = (const float4*)wk; o = oqkv + 2048 * HID;  n4 = (NKV * HD * HID) >> 2; }
    else if (t == 2) { w = (const float4*)wv; o = oqkv + 2560 * HID;  n4 = (NKV * HD * HID) >> 2; }
    else if (t == 3) { w = (const float4*)wo; o = oo;                 n4 = (HID * HID) >> 2; }
    else             { w = (const float4*)x;  o = ox;                 n4 = (S_LEN * HID) >> 2; }
    float inv = quant ? 1.f / scales[t] : 1.f;
    int stride = gridDim.x * blockDim.x;
    for (int i0 = blockIdx.x * blockDim.x + threadIdx.x; i0 < n4; i0 += 4 * stride) {
        float4 v[4];
        int cnt = 0;
#pragma unroll
        for (int j = 0; j < 4; j++) {
            int idx = i0 + j * stride;
            if (idx < n4) { v[j] = w[idx]; cnt = j + 1; }
        }
#pragma unroll
        for (int j = 0; j < 4; j++) {
            int idx = i0 + j * stride;
            if (j < cnt && idx < n4) {
                unsigned u0, u1;
                if (quant) {
                    u0 = pack_half2(rintf(fminf(fmaxf(v[j].x * inv, -1.f), 1.f)),
                                    rintf(fminf(fmaxf(v[j].y * inv, -1.f), 1.f)));
                    u1 = pack_half2(rintf(fminf(fmaxf(v[j].z * inv, -1.f), 1.f)),
                                    rintf(fminf(fmaxf(v[j].w * inv, -1.f), 1.f)));
                } else {
                    u0 = pack_half2(v[j].x, v[j].y);
                    u1 = pack_half2(v[j].z, v[j].w);
                }
                ((uint2*)o)[idx] = make_uint2(u0, u1);
            }
        }
    }
}

// ---------------- GEMM common: 128x128 block, 64x32 warp tile, 4-stage pipeline ----------------
#define GBM 128
#define GBN 128
#define GBKH 32
#define PADH 40
#define STAGES 4
#define HGEMM_SMEM (STAGES * 2 * GBM * PADH * 2)

struct Frag { float c[4][4][4]; };

__device__ __forceinline__ void hgemm_mainloop(const __half* __restrict__ Ap,
                                               const __half* __restrict__ Wp,
                                               __half* Ah, __half* Bh,
                                               int K, int tid, int wm, int wn,
                                               int lane, Frag& F) {
    const int a_row = lane & 15;
    const int a_col = (lane >> 4) * 8;
    const int b_sel = lane >> 4;
    const int b_row = lane & 7;
    const int b_col = ((lane >> 3) & 1) * 8;

    const int ntiles = K / GBKH;

    auto load_tile = [&](int stage, int k0) {
#pragma unroll
        for (int i = 0; i < 2; i++) {
            int ch = tid + i * 256;
            int r = ch >> 2, c8 = (ch & 3) * 8;
            cp_async16(Ah + stage * GBM * PADH + r * PADH + c8, Ap + (size_t)r * K + k0 + c8);
            cp_async16(Bh + stage * GBM * PADH + r * PADH + c8, Wp + (size_t)r * K + k0 + c8);
        }
    };

#pragma unroll
    for (int s = 0; s < STAGES - 1; s++) {
        load_tile(s, s * GBKH);
        cp_commit();
    }

    for (int kt = 0; kt < ntiles; kt++) {
        cp_wait<STAGES - 2>();
        __syncthreads();

        int kn = kt + STAGES - 1;
        if (kn < ntiles) load_tile(kn % STAGES, kn * GBKH);
        cp_commit();

        const __half* As = Ah + (kt % STAGES) * GBM * PADH;
        const __half* Bs = Bh + (kt % STAGES) * GBM * PADH;

#pragma unroll
        for (int ks = 0; ks < GBKH; ks += 16) {
            unsigned a[4][4], b[4][2];
#pragma unroll
            for (int mt = 0; mt < 4; mt++)
                ldsm4(a[mt], As + (wm + mt * 16 + a_row) * PADH + ks + a_col);
#pragma unroll
            for (int j = 0; j < 2; j++) {
                unsigned bb[4];
                ldsm4(bb, Bs + (wn + (2 * j + b_sel) * 8 + b_row) * PADH + ks + b_col);
                b[2 * j][0] = bb[0]; b[2 * j][1] = bb[1];
                b[2 * j + 1][0] = bb[2]; b[2 * j + 1][1] = bb[3];
            }
#pragma unroll
            for (int mt = 0; mt < 4; mt++)
#pragma unroll
                for (int nt = 0; nt < 4; nt++)
                    mma_f16(F.c[mt][nt], a[mt], b[nt]);
        }
        // no trailing __syncthreads: buffer kt%STAGES is next written at
        // iteration kt+1, after that iteration's top __syncthreads.
    }
}

// ---------------- fused QKV GEMM ----------------
__global__ __launch_bounds__(256) void hgemm_qkv(const __half* __restrict__ A,
                                                 const __half* __restrict__ Wqkv,
                                                 __half* __restrict__ Qout,
                                                 __half* __restrict__ Kout,
                                                 __half* __restrict__ Vtout,
                                                 const float* __restrict__ scales) {
    extern __shared__ __half hsm[];
    __half* Ah = hsm;
    __half* Bh = hsm + STAGES * GBM * PADH;

    const int tid = threadIdx.x;
    const int bx = blockIdx.x;
    const int bm = blockIdx.y * GBM;
    const int bn = bx * GBN;
    const int warp = tid >> 5, lane = tid & 31;
    const int wm = (warp & 1) * 64;
    const int wn = (warp >> 1) * 32;
    const int g = lane >> 2, tg = lane & 3;

    Frag F = {};
    hgemm_mainloop(A + (size_t)bm * HID, Wqkv + (size_t)bn * HID, Ah, Bh,
                   HID, tid, wm, wn, lane, F);

    const int region = bx < 16 ? 0 : (bx < 20 ? 1 : 2);
    const float scale = scales[region];

#pragma unroll
    for (int mt = 0; mt < 4; mt++) {
#pragma unroll
        for (int nt = 0; nt < 4; nt++) {
            int row = bm + wm + mt * 16 + g;
            int cb = wn + nt * 8 + 2 * tg;
            float v0 = F.c[mt][nt][0] * scale, v1 = F.c[mt][nt][1] * scale;
            float v2 = F.c[mt][nt][2] * scale, v3 = F.c[mt][nt][3] * scale;
            if (region == 0) {
                int col = bn + cb;
                *(unsigned*)(Qout + (size_t)row * HID + col) = pack_half2(v0, v1);
                *(unsigned*)(Qout + (size_t)(row + 8) * HID + col) = pack_half2(v2, v3);
            } else if (region == 1) {
                int col = bn - 2048 + cb;
                *(unsigned*)(Kout + (size_t)row * (NKV * HD) + col) = pack_half2(v0, v1);
                *(unsigned*)(Kout + (size_t)(row + 8) * (NKV * HD) + col) = pack_half2(v2, v3);
            } else {
                int col = bn - 2560 + cb;
                Vtout[(size_t)col * S_LEN + row]           = __float2half_rn(v0);
                Vtout[(size_t)(col + 1) * S_LEN + row]     = __float2half_rn(v1);
                Vtout[(size_t)col * S_LEN + row + 8]       = __float2half_rn(v2);
                Vtout[(size_t)(col + 1) * S_LEN + row + 8] = __float2half_rn(v3);
            }
        }
    }
}

// ---------------- output GEMM (fp32 out) ----------------
__global__ __launch_bounds__(256) void hgemm_out(const __half* __restrict__ A,
                                                 const __half* __restrict__ W,
                                                 float* __restrict__ C,
                                                 const float* __restrict__ scale_p) {
    extern __shared__ __half hsm[];
    __half* Ah = hsm;
    __half* Bh = hsm + STAGES * GBM * PADH;

    const int tid = threadIdx.x;
    const float scale = *scale_p;
    const int bm = blockIdx.y * GBM;
    const int bn = blockIdx.x * GBN;
    const int warp = tid >> 5, lane = tid & 31;
    const int wm = (warp & 1) * 64;
    const int wn = (warp >> 1) * 32;
    const int g = lane >> 2, tg = lane & 3;

    Frag F = {};
    hgemm_mainloop(A + (size_t)bm * HID, W + (size_t)bn * HID, Ah, Bh,
                   HID, tid, wm, wn, lane, F);

#pragma unroll
    for (int mt = 0; mt < 4; mt++) {
#pragma unroll
        for (int nt = 0; nt < 4; nt++) {
            int row = bm + wm + mt * 16 + g;
            int col = bn + wn + nt * 8 + 2 * tg;
            *(float2*)(C + (size_t)row * HID + col) =
                make_float2(F.c[mt][nt][0] * scale, F.c[mt][nt][1] * scale);
            *(float2*)(C + (size_t)(row + 8) * HID + col) =
                make_float2(F.c[mt][nt][2] * scale, F.c[mt][nt][3] * scale);
        }
    }
}

// ---------------- fused RoPE over Q and K (one launch) ----------------
__global__ void rope_qk(__half* __restrict__ q, __half* __restrict__ k,
                        const int* __restrict__ pos_ids) {
    int idx = blockIdx.x * blockDim.x + threadIdx.x;
    const int qtotal = S_LEN * NH * 32;
    const int total = qtotal + S_LEN * NKV * 32;
    if (idx >= total) return;
    __half* x;
    int nheads;
    float s_mul;
    int li;
    if (idx < qtotal) { x = q; nheads = NH; s_mul = 0.125f; li = idx; }
    else { x = k; nheads = NKV; s_mul = 1.0f; li = idx - qtotal; }
    int i = li & 31;
    int h = (li >> 5) % nheads;
    int s = li / (32 * nheads);
    float pos = (float)pos_ids[s];
    float inv_freq = powf(10000.f, -(float)(2 * i) / 64.f);
    float ang = pos * inv_freq;
    float c = cosf(ang), sn = sinf(ang);
    __half* base = x + ((size_t)s * nheads + h) * HD;
    float x1 = __half2float(base[i]), x2 = __half2float(base[i + 32]);
    base[i]      = __float2half_rn(s_mul * (x1 * c - x2 * sn));
    base[i + 32] = __float2half_rn(s_mul * (x2 * c + x1 * sn));
}

// ---------------- fp16 flash attention: 128 q-rows/block, 8 warps, KV tile 128 ----------------
// Mask staged in smem once per block (removes per-tile LDG from the softmax path).
#define KPADH 72
#define VPADT 136
#define FAH_KV ((2 * 128 * KPADH + 2 * 64 * VPADT) * 2)
#define FAH_SMEM (FAH_KV + S_LEN * 4)

__global__ __launch_bounds__(256) void flash_h(const __half* __restrict__ Qh,
                                               const __half* __restrict__ Kg,
                                               const __half* __restrict__ Vtg,
                                               const float* __restrict__ mask,
                                               __half* __restrict__ O) {
    extern __shared__ __half hs[];
    __half (*Ks)[128][KPADH] = (__half(*)[128][KPADH])hs;
    __half (*Vs)[64][VPADT] = (__half(*)[64][VPADT])(hs + 2 * 128 * KPADH);
    float* msk = (float*)(hs + FAH_KV / 2);

    const int tid = threadIdx.x;
    const int warp = tid >> 5, lane = tid & 31;
    const int g = lane >> 2, tg = lane & 3;
    const int wm = warp * 16;          // 8 warps -> 128 q rows

    const int h = blockIdx.y;
    const int kvh = h >> 2;
    const int qbase = blockIdx.x * 128;

    // stage mask once
    for (int i = tid; i < S_LEN / 4; i += 256)
        ((float4*)msk)[i] = ((const float4*)mask)[i];

    auto load_tiles = [&](int buf, int t) {
#pragma unroll
        for (int u = 0; u < 4; u++) {
            int slot = tid + u * 256;
            int kr = slot >> 3, kc = (slot & 7) * 8;
            cp_async16(&Ks[buf][kr][kc], Kg + (size_t)(t + kr) * (NKV * HD) + kvh * HD + kc);
            int vr = slot >> 4, vc = (slot & 15) * 8;
            cp_async16(&Vs[buf][vr][vc], Vtg + (size_t)(kvh * HD + vr) * S_LEN + t + vc);
        }
    };

    unsigned qa[4][4];
    {
        const __half* Qp = Qh + (size_t)qbase * HID + h * HD;
        const int r0 = wm + g, r1 = wm + g + 8;
#pragma unroll
        for (int ks = 0; ks < 4; ks++) {
            qa[ks][0] = *(const unsigned*)(Qp + (size_t)r0 * HID + ks * 16 + 2 * tg);
            qa[ks][1] = *(const unsigned*)(Qp + (size_t)r1 * HID + ks * 16 + 2 * tg);
            qa[ks][2] = *(const unsigned*)(Qp + (size_t)r0 * HID + ks * 16 + 2 * tg + 8);
            qa[ks][3] = *(const unsigned*)(Qp + (size_t)r1 * HID + ks * 16 + 2 * tg + 8);
        }
    }

    float co[8][4] = {};
    float m_g = -1e30f, m_g8 = -1e30f, l_g = 0.f, l_g8 = 0.f;

    load_tiles(0, 0);
    cp_commit();

    for (int ti = 0; ti < S_LEN / 128; ti++) {
        const int t = ti * 128;
        if (ti + 1 < S_LEN / 128) load_tiles((ti + 1) & 1, t + 128);
        cp_commit();
        cp_wait<1>();
        __syncthreads();

        const int buf = ti & 1;

        float cs[16][4] = {};
#pragma unroll
        for (int ks = 0; ks < 4; ks++) {
#pragma unroll
            for (int nt = 0; nt < 16; nt++) {
                unsigned b[2];
                b[0] = *(const unsigned*)&Ks[buf][nt * 8 + g][ks * 16 + 2 * tg];
                b[1] = *(const unsigned*)&Ks[buf][nt * 8 + g][ks * 16 + 2 * tg + 8];
                mma_f16(cs[nt], qa[ks], b);
            }
        }

        float mloc_g = -1e30f, mloc_g8 = -1e30f;
#pragma unroll
        for (int nt = 0; nt < 16; nt++) {
            float mk0 = msk[t + nt * 8 + 2 * tg];
            float mk1 = msk[t + nt * 8 + 2 * tg + 1];
            cs[nt][0] += mk0; cs[nt][1] += mk1;
            cs[nt][2] += mk0; cs[nt][3] += mk1;
            mloc_g  = fmaxf(mloc_g,  fmaxf(cs[nt][0], cs[nt][1]));
            mloc_g8 = fmaxf(mloc_g8, fmaxf(cs[nt][2], cs[nt][3]));
        }
        mloc_g  = fmaxf(mloc_g,  __shfl_xor_sync(0xffffffff, mloc_g, 1));
        mloc_g  = fmaxf(mloc_g,  __shfl_xor_sync(0xffffffff, mloc_g, 2));
        mloc_g8 = fmaxf(mloc_g8, __shfl_xor_sync(0xffffffff, mloc_g8, 1));
        mloc_g8 = fmaxf(mloc_g8, __shfl_xor_sync(0xffffffff, mloc_g8, 2));

        float mn_g  = fmaxf(m_g,  mloc_g);
        float mn_g8 = fmaxf(m_g8, mloc_g8);
        float corr_g  = __expf(m_g - mn_g);
        float corr_g8 = __expf(m_g8 - mn_g8);

        float sum_g = 0.f, sum_g8 = 0.f;
#pragma unroll
        for (int nt = 0; nt < 16; nt++) {
            cs[nt][0] = __expf(cs[nt][0] - mn_g);
            cs[nt][1] = __expf(cs[nt][1] - mn_g);
            cs[nt][2] = __expf(cs[nt][2] - mn_g8);
            cs[nt][3] = __expf(cs[nt][3] - mn_g8);
            sum_g  += cs[nt][0] + cs[nt][1];
            sum_g8 += cs[nt][2] + cs[nt][3];
        }
#pragma unroll
        for (int nt = 0; nt < 8; nt++) {
            co[nt][0] *= corr_g;  co[nt][1] *= corr_g;
            co[nt][2] *= corr_g8; co[nt][3] *= corr_g8;
        }
        sum_g  += __shfl_xor_sync(0xffffffff, sum_g, 1);
        sum_g  += __shfl_xor_sync(0xffffffff, sum_g, 2);
        sum_g8 += __shfl_xor_sync(0xffffffff, sum_g8, 1);
        sum_g8 += __shfl_xor_sync(0xffffffff, sum_g8, 2);
        l_g  = l_g * corr_g + sum_g;
        l_g8 = l_g8 * corr_g8 + sum_g8;
        m_g = mn_g; m_g8 = mn_g8;

#pragma unroll
        for (int kk = 0; kk < 8; kk++) {
            unsigned a[4];
            a[0] = pack_half2(cs[2 * kk][0],     cs[2 * kk][1]);
            a[1] = pack_half2(cs[2 * kk][2],     cs[2 * kk][3]);
            a[2] = pack_half2(cs[2 * kk + 1][0], cs[2 * kk + 1][1]);
            a[3] = pack_half2(cs[2 * kk + 1][2], cs[2 * kk + 1][3]);
#pragma unroll
            for (int nt = 0; nt < 8; nt++) {
                unsigned b[2];
                b[0] = *(const unsigned*)&Vs[buf][nt * 8 + g][kk * 16 + 2 * tg];
                b[1] = *(const unsigned*)&Vs[buf][nt * 8 + g][kk * 16 + 2 * tg + 8];
                mma_f16(co[nt], a, b);
            }
        }
        __syncthreads();   // required: next iteration's cp.async into buf^1 is
                           // issued before the top sync of that iteration.
    }

    const float inv_g  = 1.f / l_g;
    const float inv_g8 = 1.f / l_g8;
    const int row0 = qbase + wm + g;
#pragma unroll
    for (int nt = 0; nt < 8; nt++) {
        int col = h * HD + nt * 8 + 2 * tg;
        *(unsigned*)(O + (size_t)row0 * HID + col) =
            pack_half2(co[nt][0] * inv_g, co[nt][1] * inv_g);
        *(unsigned*)(O + (size_t)(row0 + 8) * HID + col) =
            pack_half2(co[nt][2] * inv_g8, co[nt][3] * inv_g8);
    }
}

// ---------------- host launcher ----------------
extern "C" void kernel_launch(void* const* d_in, const int* in_sizes, int n_in,
                              void* d_out, int out_size) {
    const float* x    = (const float*)d_in[0];
    const float* mask = (const float*)d_in[1];
    const int*   pos  = (const int*)d_in[2];
    const float* wq   = (const float*)d_in[3];
    const float* wk   = (const float*)d_in[4];
    const float* wv   = (const float*)d_in[5];
    const float* wo   = (const float*)d_in[6];
    float* out = (float*)d_out;

    float *pscale, *ppart;
    __half *pxh, *pwqkv, *pwo, *pqh, *pkh, *pvth, *patth;
    cudaGetSymbolAddress((void**)&pscale, g_scale);
    cudaGetSymbolAddress((void**)&ppart,  g_part);
    cudaGetSymbolAddress((void**)&pxh,    g_xh);
    cudaGetSymbolAddress((void**)&pwqkv,  g_wqkv);
    cudaGetSymbolAddress((void**)&pwo,    g_wo);
    cudaGetSymbolAddress((void**)&pqh,    g_qh);
    cudaGetSymbolAddress((void**)&pkh,    g_kh);
    cudaGetSymbolAddress((void**)&pvth,   g_vth);
    cudaGetSymbolAddress((void**)&patth,  g_atth);

    cudaFuncSetAttribute(hgemm_qkv, cudaFuncAttributeMaxDynamicSharedMemorySize, HGEMM_SMEM);
    cudaFuncSetAttribute(hgemm_out, cudaFuncAttributeMaxDynamicSharedMemorySize, HGEMM_SMEM);
    cudaFuncSetAttribute(flash_h, cudaFuncAttributeMaxDynamicSharedMemorySize, FAH_SMEM);

    // scales
    absmean_all_partial<<<dim3(256, 4), 256>>>(wq, wk, wv, wo, ppart);
    absmean_all_final<<<4, 256>>>(ppart, pscale);

    // fused pre-pass: weight quantize + x convert in one launch
    prep_all_h<<<dim3(256, 5), 256>>>(wq, wk, wv, wo, x, pwqkv, pwo, pxh, pscale);

    // fused QKV projection (128x128 tiles, 4-stage pipeline)
    hgemm_qkv<<<dim3(24, 16), 256, HGEMM_SMEM>>>(pxh, pwqkv, pqh, pkh, pvth, pscale);

    // RoPE (Q pre-scaled by 1/sqrt(64)), single launch
    rope_qk<<<(S_LEN * (NH + NKV) * 32 + 255) / 256, 256>>>(pqh, pkh, pos);

    // flash attention (128 q-rows x 128 kv tile, 8 warps, mask in smem)
    flash_h<<<dim3(S_LEN / 128, NH), 256, FAH_SMEM>>>(pqh, pkh, pvth, mask, patth);

    // output projection
    hgemm_out<<<dim3(16, 16), 256, HGEMM_SMEM>>>(patth, pwo, out, pscale + 3);
}

// round 17
// speedup vs baseline: 1.2006x; 1.0217x over previous
#include <cuda_runtime.h>
#include <cuda_fp16.h>
#include <math.h>

#define S_LEN 2048
#define HID   2048
#define NH    32
#define NKV   8
#define HD    64
#define LOG2E 1.4426950408889634f

// ---------------- static scratch ----------------
static __device__ float  g_scale[4];
static __device__ float  g_part[4 * 256];
static __device__ __half g_xh[S_LEN * HID];            // fp16 activations
static __device__ __half g_wqkv[3072 * HID];           // concat ternary: Q[0:2048) K[2048:2560) V[2560:3072)
static __device__ __half g_wo[HID * HID];
static __device__ __half g_qh[S_LEN * HID];            // Q (rope'd, pre-scaled log2e/8)
static __device__ __half g_kh[S_LEN * NKV * HD];       // K (rope'd)
static __device__ __half g_vth[NKV * HD * S_LEN];      // V TRANSPOSED [d][seq]
static __device__ __half g_atth[S_LEN * HID];          // attention out

// ---------------- helpers ----------------
__device__ __forceinline__ unsigned pack_half2(float lo, float hi) {
    __half2 h = __floats2half2_rn(lo, hi);
    return *(unsigned*)&h;
}

__device__ __forceinline__ float fexp2(float x) {
    float r;
    asm("ex2.approx.ftz.f32 %0, %1;" : "=f"(r) : "f"(x));
    return r;
}

__device__ __forceinline__ void mma_f16(float c[4], const unsigned a[4], const unsigned b[2]) {
    asm volatile(
        "mma.sync.aligned.m16n8k16.row.col.f32.f16.f16.f32 "
        "{%0,%1,%2,%3}, {%4,%5,%6,%7}, {%8,%9}, {%0,%1,%2,%3};"
        : "+f"(c[0]), "+f"(c[1]), "+f"(c[2]), "+f"(c[3])
        : "r"(a[0]), "r"(a[1]), "r"(a[2]), "r"(a[3]), "r"(b[0]), "r"(b[1]));
}

__device__ __forceinline__ void ldsm4(unsigned r[4], const __half* p) {
    unsigned addr = (unsigned)__cvta_generic_to_shared(p);
    asm volatile("ldmatrix.sync.aligned.m8n8.x4.shared.b16 {%0,%1,%2,%3}, [%4];"
                 : "=r"(r[0]), "=r"(r[1]), "=r"(r[2]), "=r"(r[3]) : "r"(addr));
}

__device__ __forceinline__ void cp_async16(void* smem_dst, const void* gptr) {
    unsigned s = (unsigned)__cvta_generic_to_shared(smem_dst);
    asm volatile("cp.async.cg.shared.global [%0], [%1], 16;" :: "r"(s), "l"(gptr));
}
__device__ __forceinline__ void cp_commit() { asm volatile("cp.async.commit_group;"); }
template <int N>
__device__ __forceinline__ void cp_wait() { asm volatile("cp.async.wait_group %0;" :: "n"(N)); }

// ---------------- absmean partial (deterministic) ----------------
__global__ void absmean_all_partial(const float* __restrict__ wq, const float* __restrict__ wk,
                                    const float* __restrict__ wv, const float* __restrict__ wo,
                                    float* __restrict__ part) {
    __shared__ float red[256];
    int t = blockIdx.y;
    const float* w = t == 0 ? wq : t == 1 ? wk : t == 2 ? wv : wo;
    int n = (t == 0 || t == 3) ? HID * HID : NKV * HD * HID;
    float s0 = 0.f, s1 = 0.f, s2 = 0.f, s3 = 0.f;
    int stride = gridDim.x * blockDim.x;
    for (int i = blockIdx.x * blockDim.x + threadIdx.x; i < n; i += 4 * stride) {
        s0 += fabsf(w[i]);
        if (i + stride < n)     s1 += fabsf(w[i + stride]);
        if (i + 2 * stride < n) s2 += fabsf(w[i + 2 * stride]);
        if (i + 3 * stride < n) s3 += fabsf(w[i + 3 * stride]);
    }
    red[threadIdx.x] = (s0 + s1) + (s2 + s3);
    __syncthreads();
    for (int o = 128; o > 0; o >>= 1) {
        if (threadIdx.x < o) red[threadIdx.x] += red[threadIdx.x + o];
        __syncthreads();
    }
    if (threadIdx.x == 0) part[t * 256 + blockIdx.x] = red[0];
}

// ---------------- fused: absmean final + quantize (w->ternary fp16) + x->fp16 ----------------
// blockIdx.y: 0..3 = weight quantize (computes its own scale from partials, block 0 publishes),
//             4 = x convert.
__global__ void prep_all_h(const float* __restrict__ wq, const float* __restrict__ wk,
                           const float* __restrict__ wv, const float* __restrict__ wo,
                           const float* __restrict__ x,
                           __half* __restrict__ oqkv, __half* __restrict__ oo,
                           __half* __restrict__ ox,
                           const float* __restrict__ part,
                           float* __restrict__ scales_out) {
    __shared__ float red[256];
    int t = blockIdx.y;
    const float4* w;
    __half* o;
    int n4;
    bool quant = t < 4;
    if (t == 0)      { w = (const float4*)wq; o = oqkv;               n4 = (HID * HID) >> 2; }
    else if (t == 1) { w = (const float4*)wk; o = oqkv + 2048 * HID;  n4 = (NKV * HD * HID) >> 2; }
    else if (t == 2) { w = (const float4*)wv; o = oqkv + 2560 * HID;  n4 = (NKV * HD * HID) >> 2; }
    else if (t == 3) { w = (const float4*)wo; o = oo;                 n4 = (HID * HID) >> 2; }
    else             { w = (const float4*)x;  o = ox;                 n4 = (S_LEN * HID) >> 2; }

    float inv = 1.f;
    if (quant) {
        // identical tree reduction to the old absmean_final (bit-identical scale)
        red[threadIdx.x] = part[t * 256 + threadIdx.x];
        __syncthreads();
        for (int oo2 = 128; oo2 > 0; oo2 >>= 1) {
            if (threadIdx.x < oo2) red[threadIdx.x] += red[threadIdx.x + oo2];
            __syncthreads();
        }
        float scale = red[0] / (float)(n4 * 4) + 1e-6f;
        if (blockIdx.x == 0 && threadIdx.x == 0) scales_out[t] = scale;
        inv = 1.f / scale;
    }

    int stride = gridDim.x * blockDim.x;
    for (int i0 = blockIdx.x * blockDim.x + threadIdx.x; i0 < n4; i0 += 4 * stride) {
        float4 v[4];
        int cnt = 0;
#pragma unroll
        for (int j = 0; j < 4; j++) {
            int idx = i0 + j * stride;
            if (idx < n4) { v[j] = w[idx]; cnt = j + 1; }
        }
#pragma unroll
        for (int j = 0; j < 4; j++) {
            int idx = i0 + j * stride;
            if (j < cnt && idx < n4) {
                unsigned u0, u1;
                if (quant) {
                    u0 = pack_half2(rintf(fminf(fmaxf(v[j].x * inv, -1.f), 1.f)),
                                    rintf(fminf(fmaxf(v[j].y * inv, -1.f), 1.f)));
                    u1 = pack_half2(rintf(fminf(fmaxf(v[j].z * inv, -1.f), 1.f)),
                                    rintf(fminf(fmaxf(v[j].w * inv, -1.f), 1.f)));
                } else {
                    u0 = pack_half2(v[j].x, v[j].y);
                    u1 = pack_half2(v[j].z, v[j].w);
                }
                ((uint2*)o)[idx] = make_uint2(u0, u1);
            }
        }
    }
}

// ---------------- GEMM common: 128x128 block, 64x32 warp tile, 4-stage pipeline ----------------
#define GBM 128
#define GBN 128
#define GBKH 32
#define PADH 40
#define STAGES 4
#define HGEMM_SMEM (STAGES * 2 * GBM * PADH * 2)

struct Frag { float c[4][4][4]; };

__device__ __forceinline__ void hgemm_mainloop(const __half* __restrict__ Ap,
                                               const __half* __restrict__ Wp,
                                               __half* Ah, __half* Bh,
                                               int K, int tid, int wm, int wn,
                                               int lane, Frag& F) {
    const int a_row = lane & 15;
    const int a_col = (lane >> 4) * 8;
    const int b_sel = lane >> 4;
    const int b_row = lane & 7;
    const int b_col = ((lane >> 3) & 1) * 8;

    const int ntiles = K / GBKH;

    auto load_tile = [&](int stage, int k0) {
#pragma unroll
        for (int i = 0; i < 2; i++) {
            int ch = tid + i * 256;
            int r = ch >> 2, c8 = (ch & 3) * 8;
            cp_async16(Ah + stage * GBM * PADH + r * PADH + c8, Ap + (size_t)r * K + k0 + c8);
            cp_async16(Bh + stage * GBM * PADH + r * PADH + c8, Wp + (size_t)r * K + k0 + c8);
        }
    };

#pragma unroll
    for (int s = 0; s < STAGES - 1; s++) {
        load_tile(s, s * GBKH);
        cp_commit();
    }

    for (int kt = 0; kt < ntiles; kt++) {
        cp_wait<STAGES - 2>();
        __syncthreads();

        int kn = kt + STAGES - 1;
        if (kn < ntiles) load_tile(kn % STAGES, kn * GBKH);
        cp_commit();

        const __half* As = Ah + (kt % STAGES) * GBM * PADH;
        const __half* Bs = Bh + (kt % STAGES) * GBM * PADH;

#pragma unroll
        for (int ks = 0; ks < GBKH; ks += 16) {
            unsigned a[4][4], b[4][2];
#pragma unroll
            for (int mt = 0; mt < 4; mt++)
                ldsm4(a[mt], As + (wm + mt * 16 + a_row) * PADH + ks + a_col);
#pragma unroll
            for (int j = 0; j < 2; j++) {
                unsigned bb[4];
                ldsm4(bb, Bs + (wn + (2 * j + b_sel) * 8 + b_row) * PADH + ks + b_col);
                b[2 * j][0] = bb[0]; b[2 * j][1] = bb[1];
                b[2 * j + 1][0] = bb[2]; b[2 * j + 1][1] = bb[3];
            }
#pragma unroll
            for (int mt = 0; mt < 4; mt++)
#pragma unroll
                for (int nt = 0; nt < 4; nt++)
                    mma_f16(F.c[mt][nt], a[mt], b[nt]);
        }
        // no trailing __syncthreads: buffer kt%STAGES is next written at
        // iteration kt+1, after that iteration's top __syncthreads.
    }
}

// ---------------- fused QKV GEMM ----------------
__global__ __launch_bounds__(256) void hgemm_qkv(const __half* __restrict__ A,
                                                 const __half* __restrict__ Wqkv,
                                                 __half* __restrict__ Qout,
                                                 __half* __restrict__ Kout,
                                                 __half* __restrict__ Vtout,
                                                 const float* __restrict__ scales) {
    extern __shared__ __half hsm[];
    __half* Ah = hsm;
    __half* Bh = hsm + STAGES * GBM * PADH;

    const int tid = threadIdx.x;
    const int bx = blockIdx.x;
    const int bm = blockIdx.y * GBM;
    const int bn = bx * GBN;
    const int warp = tid >> 5, lane = tid & 31;
    const int wm = (warp & 1) * 64;
    const int wn = (warp >> 1) * 32;
    const int g = lane >> 2, tg = lane & 3;

    Frag F = {};
    hgemm_mainloop(A + (size_t)bm * HID, Wqkv + (size_t)bn * HID, Ah, Bh,
                   HID, tid, wm, wn, lane, F);

    const int region = bx < 16 ? 0 : (bx < 20 ? 1 : 2);
    const float scale = scales[region];

#pragma unroll
    for (int mt = 0; mt < 4; mt++) {
#pragma unroll
        for (int nt = 0; nt < 4; nt++) {
            int row = bm + wm + mt * 16 + g;
            int cb = wn + nt * 8 + 2 * tg;
            float v0 = F.c[mt][nt][0] * scale, v1 = F.c[mt][nt][1] * scale;
            float v2 = F.c[mt][nt][2] * scale, v3 = F.c[mt][nt][3] * scale;
            if (region == 0) {
                int col = bn + cb;
                *(unsigned*)(Qout + (size_t)row * HID + col) = pack_half2(v0, v1);
                *(unsigned*)(Qout + (size_t)(row + 8) * HID + col) = pack_half2(v2, v3);
            } else if (region == 1) {
                int col = bn - 2048 + cb;
                *(unsigned*)(Kout + (size_t)row * (NKV * HD) + col) = pack_half2(v0, v1);
                *(unsigned*)(Kout + (size_t)(row + 8) * (NKV * HD) + col) = pack_half2(v2, v3);
            } else {
                int col = bn - 2560 + cb;
                Vtout[(size_t)col * S_LEN + row]           = __float2half_rn(v0);
                Vtout[(size_t)(col + 1) * S_LEN + row]     = __float2half_rn(v1);
                Vtout[(size_t)col * S_LEN + row + 8]       = __float2half_rn(v2);
                Vtout[(size_t)(col + 1) * S_LEN + row + 8] = __float2half_rn(v3);
            }
        }
    }
}

// ---------------- output GEMM (fp32 out) ----------------
__global__ __launch_bounds__(256) void hgemm_out(const __half* __restrict__ A,
                                                 const __half* __restrict__ W,
                                                 float* __restrict__ C,
                                                 const float* __restrict__ scale_p) {
    extern __shared__ __half hsm[];
    __half* Ah = hsm;
    __half* Bh = hsm + STAGES * GBM * PADH;

    const int tid = threadIdx.x;
    const float scale = *scale_p;
    const int bm = blockIdx.y * GBM;
    const int bn = blockIdx.x * GBN;
    const int warp = tid >> 5, lane = tid & 31;
    const int wm = (warp & 1) * 64;
    const int wn = (warp >> 1) * 32;
    const int g = lane >> 2, tg = lane & 3;

    Frag F = {};
    hgemm_mainloop(A + (size_t)bm * HID, W + (size_t)bn * HID, Ah, Bh,
                   HID, tid, wm, wn, lane, F);

#pragma unroll
    for (int mt = 0; mt < 4; mt++) {
#pragma unroll
        for (int nt = 0; nt < 4; nt++) {
            int row = bm + wm + mt * 16 + g;
            int col = bn + wn + nt * 8 + 2 * tg;
            *(float2*)(C + (size_t)row * HID + col) =
                make_float2(F.c[mt][nt][0] * scale, F.c[mt][nt][1] * scale);
            *(float2*)(C + (size_t)(row + 8) * HID + col) =
                make_float2(F.c[mt][nt][2] * scale, F.c[mt][nt][3] * scale);
        }
    }
}

// ---------------- fused RoPE over Q and K (one launch) ----------------
// Q pre-scaled by log2(e)/8 so flash scores land in the exp2 domain.
__global__ void rope_qk(__half* __restrict__ q, __half* __restrict__ k,
                        const int* __restrict__ pos_ids) {
    int idx = blockIdx.x * blockDim.x + threadIdx.x;
    const int qtotal = S_LEN * NH * 32;
    const int total = qtotal + S_LEN * NKV * 32;
    if (idx >= total) return;
    __half* x;
    int nheads;
    float s_mul;
    int li;
    if (idx < qtotal) { x = q; nheads = NH; s_mul = 0.125f * LOG2E; li = idx; }
    else { x = k; nheads = NKV; s_mul = 1.0f; li = idx - qtotal; }
    int i = li & 31;
    int h = (li >> 5) % nheads;
    int s = li / (32 * nheads);
    float pos = (float)pos_ids[s];
    float inv_freq = powf(10000.f, -(float)(2 * i) / 64.f);
    float ang = pos * inv_freq;
    float c = cosf(ang), sn = sinf(ang);
    __half* base = x + ((size_t)s * nheads + h) * HD;
    float x1 = __half2float(base[i]), x2 = __half2float(base[i + 32]);
    base[i]      = __float2half_rn(s_mul * (x1 * c - x2 * sn));
    base[i + 32] = __float2half_rn(s_mul * (x2 * c + x1 * sn));
}

// ---------------- fp16 flash attention: 128 q-rows/block, 8 warps, KV tile 128 ----------------
// Mask staged in smem pre-scaled by log2(e); softmax runs in base-2 (bare ex2.approx).
#define KPADH 72
#define VPADT 136
#define FAH_KV ((2 * 128 * KPADH + 2 * 64 * VPADT) * 2)
#define FAH_SMEM (FAH_KV + S_LEN * 4)

__global__ __launch_bounds__(256) void flash_h(const __half* __restrict__ Qh,
                                               const __half* __restrict__ Kg,
                                               const __half* __restrict__ Vtg,
                                               const float* __restrict__ mask,
                                               __half* __restrict__ O) {
    extern __shared__ __half hs[];
    __half (*Ks)[128][KPADH] = (__half(*)[128][KPADH])hs;
    __half (*Vs)[64][VPADT] = (__half(*)[64][VPADT])(hs + 2 * 128 * KPADH);
    float* msk = (float*)(hs + FAH_KV / 2);

    const int tid = threadIdx.x;
    const int warp = tid >> 5, lane = tid & 31;
    const int g = lane >> 2, tg = lane & 3;
    const int wm = warp * 16;          // 8 warps -> 128 q rows

    const int h = blockIdx.y;
    const int kvh = h >> 2;
    const int qbase = blockIdx.x * 128;

    // stage mask once, pre-scaled into the base-2 domain
    for (int i = tid; i < S_LEN / 4; i += 256) {
        float4 m4 = ((const float4*)mask)[i];
        m4.x *= LOG2E; m4.y *= LOG2E; m4.z *= LOG2E; m4.w *= LOG2E;
        ((float4*)msk)[i] = m4;
    }

    auto load_tiles = [&](int buf, int t) {
#pragma unroll
        for (int u = 0; u < 4; u++) {
            int slot = tid + u * 256;
            int kr = slot >> 3, kc = (slot & 7) * 8;
            cp_async16(&Ks[buf][kr][kc], Kg + (size_t)(t + kr) * (NKV * HD) + kvh * HD + kc);
            int vr = slot >> 4, vc = (slot & 15) * 8;
            cp_async16(&Vs[buf][vr][vc], Vtg + (size_t)(kvh * HD + vr) * S_LEN + t + vc);
        }
    };

    unsigned qa[4][4];
    {
        const __half* Qp = Qh + (size_t)qbase * HID + h * HD;
        const int r0 = wm + g, r1 = wm + g + 8;
#pragma unroll
        for (int ks = 0; ks < 4; ks++) {
            qa[ks][0] = *(const unsigned*)(Qp + (size_t)r0 * HID + ks * 16 + 2 * tg);
            qa[ks][1] = *(const unsigned*)(Qp + (size_t)r1 * HID + ks * 16 + 2 * tg);
            qa[ks][2] = *(const unsigned*)(Qp + (size_t)r0 * HID + ks * 16 + 2 * tg + 8);
            qa[ks][3] = *(const unsigned*)(Qp + (size_t)r1 * HID + ks * 16 + 2 * tg + 8);
        }
    }

    float co[8][4] = {};
    float m_g = -1e30f, m_g8 = -1e30f, l_g = 0.f, l_g8 = 0.f;

    load_tiles(0, 0);
    cp_commit();

    for (int ti = 0; ti < S_LEN / 128; ti++) {
        const int t = ti * 128;
        if (ti + 1 < S_LEN / 128) load_tiles((ti + 1) & 1, t + 128);
        cp_commit();
        cp_wait<1>();
        __syncthreads();

        const int buf = ti & 1;

        float cs[16][4] = {};
#pragma unroll
        for (int ks = 0; ks < 4; ks++) {
#pragma unroll
            for (int nt = 0; nt < 16; nt++) {
                unsigned b[2];
                b[0] = *(const unsigned*)&Ks[buf][nt * 8 + g][ks * 16 + 2 * tg];
                b[1] = *(const unsigned*)&Ks[buf][nt * 8 + g][ks * 16 + 2 * tg + 8];
                mma_f16(cs[nt], qa[ks], b);
            }
        }

        float mloc_g = -1e30f, mloc_g8 = -1e30f;
#pragma unroll
        for (int nt = 0; nt < 16; nt++) {
            float mk0 = msk[t + nt * 8 + 2 * tg];
            float mk1 = msk[t + nt * 8 + 2 * tg + 1];
            cs[nt][0] += mk0; cs[nt][1] += mk1;
            cs[nt][2] += mk0; cs[nt][3] += mk1;
            mloc_g  = fmaxf(mloc_g,  fmaxf(cs[nt][0], cs[nt][1]));
            mloc_g8 = fmaxf(mloc_g8, fmaxf(cs[nt][2], cs[nt][3]));
        }
        mloc_g  = fmaxf(mloc_g,  __shfl_xor_sync(0xffffffff, mloc_g, 1));
        mloc_g  = fmaxf(mloc_g,  __shfl_xor_sync(0xffffffff, mloc_g, 2));
        mloc_g8 = fmaxf(mloc_g8, __shfl_xor_sync(0xffffffff, mloc_g8, 1));
        mloc_g8 = fmaxf(mloc_g8, __shfl_xor_sync(0xffffffff, mloc_g8, 2));

        float mn_g  = fmaxf(m_g,  mloc_g);
        float mn_g8 = fmaxf(m_g8, mloc_g8);
        float corr_g  = fexp2(m_g - mn_g);
        float corr_g8 = fexp2(m_g8 - mn_g8);

        float sum_g = 0.f, sum_g8 = 0.f;
#pragma unroll
        for (int nt = 0; nt < 16; nt++) {
            cs[nt][0] = fexp2(cs[nt][0] - mn_g);
            cs[nt][1] = fexp2(cs[nt][1] - mn_g);
            cs[nt][2] = fexp2(cs[nt][2] - mn_g8);
            cs[nt][3] = fexp2(cs[nt][3] - mn_g8);
            sum_g  += cs[nt][0] + cs[nt][1];
            sum_g8 += cs[nt][2] + cs[nt][3];
        }
#pragma unroll
        for (int nt = 0; nt < 8; nt++) {
            co[nt][0] *= corr_g;  co[nt][1] *= corr_g;
            co[nt][2] *= corr_g8; co[nt][3] *= corr_g8;
        }
        sum_g  += __shfl_xor_sync(0xffffffff, sum_g, 1);
        sum_g  += __shfl_xor_sync(0xffffffff, sum_g, 2);
        sum_g8 += __shfl_xor_sync(0xffffffff, sum_g8, 1);
        sum_g8 += __shfl_xor_sync(0xffffffff, sum_g8, 2);
        l_g  = l_g * corr_g + sum_g;
        l_g8 = l_g8 * corr_g8 + sum_g8;
        m_g = mn_g; m_g8 = mn_g8;

#pragma unroll
        for (int kk = 0; kk < 8; kk++) {
            unsigned a[4];
            a[0] = pack_half2(cs[2 * kk][0],     cs[2 * kk][1]);
            a[1] = pack_half2(cs[2 * kk][2],     cs[2 * kk][3]);
            a[2] = pack_half2(cs[2 * kk + 1][0], cs[2 * kk + 1][1]);
            a[3] = pack_half2(cs[2 * kk + 1][2], cs[2 * kk + 1][3]);
#pragma unroll
            for (int nt = 0; nt < 8; nt++) {
                unsigned b[2];
                b[0] = *(const unsigned*)&Vs[buf][nt * 8 + g][kk * 16 + 2 * tg];
                b[1] = *(const unsigned*)&Vs[buf][nt * 8 + g][kk * 16 + 2 * tg + 8];
                mma_f16(co[nt], a, b);
            }
        }
        __syncthreads();   // required: next iteration's cp.async into buf^1 is
                           // issued before the top sync of that iteration.
    }

    const float inv_g  = 1.f / l_g;
    const float inv_g8 = 1.f / l_g8;
    const int row0 = qbase + wm + g;
#pragma unroll
    for (int nt = 0; nt < 8; nt++) {
        int col = h * HD + nt * 8 + 2 * tg;
        *(unsigned*)(O + (size_t)row0 * HID + col) =
            pack_half2(co[nt][0] * inv_g, co[nt][1] * inv_g);
        *(unsigned*)(O + (size_t)(row0 + 8) * HID + col) =
            pack_half2(co[nt][2] * inv_g8, co[nt][3] * inv_g8);
    }
}

// ---------------- host launcher ----------------
extern "C" void kernel_launch(void* const* d_in, const int* in_sizes, int n_in,
                              void* d_out, int out_size) {
    const float* x    = (const float*)d_in[0];
    const float* mask = (const float*)d_in[1];
    const int*   pos  = (const int*)d_in[2];
    const float* wq   = (const float*)d_in[3];
    const float* wk   = (const float*)d_in[4];
    const float* wv   = (const float*)d_in[5];
    const float* wo   = (const float*)d_in[6];
    float* out = (float*)d_out;

    float *pscale, *ppart;
    __half *pxh, *pwqkv, *pwo, *pqh, *pkh, *pvth, *patth;
    cudaGetSymbolAddress((void**)&pscale, g_scale);
    cudaGetSymbolAddress((void**)&ppart,  g_part);
    cudaGetSymbolAddress((void**)&pxh,    g_xh);
    cudaGetSymbolAddress((void**)&pwqkv,  g_wqkv);
    cudaGetSymbolAddress((void**)&pwo,    g_wo);
    cudaGetSymbolAddress((void**)&pqh,    g_qh);
    cudaGetSymbolAddress((void**)&pkh,    g_kh);
    cudaGetSymbolAddress((void**)&pvth,   g_vth);
    cudaGetSymbolAddress((void**)&patth,  g_atth);

    cudaFuncSetAttribute(hgemm_qkv, cudaFuncAttributeMaxDynamicSharedMemorySize, HGEMM_SMEM);
    cudaFuncSetAttribute(hgemm_out, cudaFuncAttributeMaxDynamicSharedMemorySize, HGEMM_SMEM);
    cudaFuncSetAttribute(flash_h, cudaFuncAttributeMaxDynamicSharedMemorySize, FAH_SMEM);

    // scale partials
    absmean_all_partial<<<dim3(256, 4), 256>>>(wq, wk, wv, wo, ppart);

    // fused pre-pass: per-block scale finalize + weight quantize + x convert
    prep_all_h<<<dim3(384, 5), 256>>>(wq, wk, wv, wo, x, pwqkv, pwo, pxh, ppart, pscale);

    // fused QKV projection (128x128 tiles, 4-stage pipeline)
    hgemm_qkv<<<dim3(24, 16), 256, HGEMM_SMEM>>>(pxh, pwqkv, pqh, pkh, pvth, pscale);

    // RoPE (Q pre-scaled by log2e/8), single launch
    rope_qk<<<(S_LEN * (NH + NKV) * 32 + 255) / 256, 256>>>(pqh, pkh, pos);

    // flash attention (128 q-rows x 128 kv tile, 8 warps, base-2 softmax, mask in smem)
    flash_h<<<dim3(S_LEN / 128, NH), 256, FAH_SMEM>>>(pqh, pkh, pvth, mask, patth);

    // output projection
    hgemm_out<<<dim3(16, 16), 256, HGEMM_SMEM>>>(patth, pwo, out, pscale + 3);
}